// round 1
// baseline (speedup 1.0000x reference)
#include <cuda_runtime.h>

// ---------------- problem constants (fixed by the reference) ----------------
#define EMBD   256
#define HIDDEN 256
#define LNUM   4
#define HNUM   8
#define PNUM   4
#define CHD    32
#define BATCH  8
#define NQ     1024
#define ITOT   21760           // 128^2 + 64^2 + 32^2 + 16^2
#define QPW    384             // H*L*P*3

// ---------------- scratch (no allocations allowed) ----------------
__device__ float  g_img_p[BATCH * ITOT * HIDDEN];     // projected pyramid  (~178 MB)
__device__ float  g_qp[BATCH * NQ * QPW];             // query projection
__device__ float  g_attn[BATCH * NQ * HNUM * 16];     // softmaxed attention
__device__ float2 g_coords[BATCH * NQ * HNUM * 16];   // sampling points (normalized)
__device__ float  g_hidden[BATCH * NQ * HIDDEN];      // sampled context

__constant__ int c_sh[4]    = {128, 64, 32, 16};
__constant__ int c_start[4] = {0, 16384, 20480, 21504};

// ---------------- classic 128x128x8 SGEMM with bias ----------------
// C[M,N] = A[M,K] @ W[K,N] + bias[N].  Requires M%128==0, N%128==0, K%8==0.
__global__ __launch_bounds__(256) void sgemm_bias(
    const float* __restrict__ A, const float* __restrict__ W,
    const float* __restrict__ bias, float* __restrict__ C,
    int M, int N, int K)
{
    __shared__ float As[8][128];
    __shared__ float Bs[8][128];

    const int tid = threadIdx.x;
    const int m0 = blockIdx.y * 128;
    const int n0 = blockIdx.x * 128;

    const int a_row = tid >> 1;            // 0..127
    const int a_col = (tid & 1) * 4;       // 0 or 4
    const int b_row = tid >> 5;            // 0..7
    const int b_col = (tid & 31) * 4;      // 0..124

    const int ty = tid >> 4;               // 0..15
    const int tx = tid & 15;               // 0..15
    const int row_base = ty * 8;
    const int col_base = tx * 8;

    const float* Aptr = A + (long)(m0 + a_row) * K + a_col;
    const float* Wptr = W + (long)b_row * N + n0 + b_col;

    float acc[8][8];
    #pragma unroll
    for (int i = 0; i < 8; i++)
        #pragma unroll
        for (int j = 0; j < 8; j++) acc[i][j] = 0.f;

    for (int kt = 0; kt < K; kt += 8) {
        float4 av = *(const float4*)(Aptr + kt);
        float4 bv = *(const float4*)(Wptr + (long)kt * N);

        __syncthreads();
        As[a_col + 0][a_row] = av.x;
        As[a_col + 1][a_row] = av.y;
        As[a_col + 2][a_row] = av.z;
        As[a_col + 3][a_row] = av.w;
        *(float4*)&Bs[b_row][b_col] = bv;
        __syncthreads();

        #pragma unroll
        for (int k = 0; k < 8; k++) {
            float a[8], b[8];
            *(float4*)(a)     = *(const float4*)&As[k][row_base];
            *(float4*)(a + 4) = *(const float4*)&As[k][row_base + 4];
            *(float4*)(b)     = *(const float4*)&Bs[k][col_base];
            *(float4*)(b + 4) = *(const float4*)&Bs[k][col_base + 4];
            #pragma unroll
            for (int i = 0; i < 8; i++)
                #pragma unroll
                for (int j = 0; j < 8; j++)
                    acc[i][j] = fmaf(a[i], b[j], acc[i][j]);
        }
    }

    float bb[8];
    #pragma unroll
    for (int j = 0; j < 8; j++) bb[j] = bias[n0 + col_base + j];

    #pragma unroll
    for (int i = 0; i < 8; i++) {
        float* crow = C + (long)(m0 + row_base + i) * N + n0 + col_base;
        float4 v0 = make_float4(acc[i][0] + bb[0], acc[i][1] + bb[1],
                                acc[i][2] + bb[2], acc[i][3] + bb[3]);
        float4 v1 = make_float4(acc[i][4] + bb[4], acc[i][5] + bb[5],
                                acc[i][6] + bb[6], acc[i][7] + bb[7]);
        *(float4*)(crow)     = v0;
        *(float4*)(crow + 4) = v1;
    }
}

// ---------------- softmax + sampling-coordinate precompute ----------------
// One thread per (b,n,h). qp layout per (b,n,h): 48 floats = [l*4+p][3] (ox, oy, logit).
// Reference convention: x-offset divided by shapes[l,0]=hh, y-offset by shapes[l,1]=ww.
// (square levels here, both equal c_sh[l])
__global__ void softmax_coords(const float* __restrict__ qp,
                               const float* __restrict__ refpts,
                               float* __restrict__ attn,
                               float2* __restrict__ coords)
{
    int t = blockIdx.x * blockDim.x + threadIdx.x;   // (b*NQ+n)*HNUM + h
    if (t >= BATCH * NQ * HNUM) return;
    int bn = t / HNUM;

    const float* q = qp + (long)t * 48;

    float lg[16];
    float mx = -1e30f;
    #pragma unroll
    for (int s = 0; s < 16; s++) { lg[s] = q[s * 3 + 2]; mx = fmaxf(mx, lg[s]); }
    float sum = 0.f;
    #pragma unroll
    for (int s = 0; s < 16; s++) { lg[s] = expf(lg[s] - mx); sum += lg[s]; }
    float inv = 1.0f / sum;

    float rx = refpts[bn * 2 + 0];
    float ry = refpts[bn * 2 + 1];

    #pragma unroll
    for (int s = 0; s < 16; s++) {
        int l = s >> 2;
        float sh = (float)c_sh[l];
        attn[(long)t * 16 + s] = lg[s] * inv;
        float ox = q[s * 3 + 0];
        float oy = q[s * 3 + 1];
        coords[(long)t * 16 + s] = make_float2(rx + ox / sh, ry + oy / sh);
    }
}

// ---------------- bilinear sampling + attention reduce ----------------
// One warp per (b,n,h); lane = channel within the head's 32-channel slice.
// Every corner gather is a single coalesced 128B warp-load from g_img_p.
__global__ __launch_bounds__(256) void msda_sample(
    const float* __restrict__ img_p,
    const float* __restrict__ attn,
    const float2* __restrict__ coords,
    float* __restrict__ out)
{
    int w = blockIdx.x * 8 + (threadIdx.x >> 5);   // (b*NQ+n)*HNUM + h
    int lane = threadIdx.x & 31;

    int h = w % HNUM;
    int b = w / (NQ * HNUM);

    const long img_base = (long)b * ITOT * HIDDEN + h * CHD + lane;
    const float*  ap = attn   + (long)w * 16;
    const float2* cp = coords + (long)w * 16;

    float acc = 0.f;

    #pragma unroll
    for (int s = 0; s < 16; s++) {
        int l = s >> 2;
        int sh = c_sh[l];
        float fs = (float)sh;
        int st = c_start[l];

        float aw = ap[s];
        float2 c = cp[s];

        float x = c.x * fs - 0.5f;
        float y = c.y * fs - 0.5f;
        float x0f = floorf(x), y0f = floorf(y);
        int x0 = (int)x0f, y0 = (int)y0f;
        float wx = x - x0f, wy = y - y0f;

        float w00 = (1.f - wx) * (1.f - wy) * aw;
        float w10 = wx * (1.f - wy) * aw;
        float w01 = (1.f - wx) * wy * aw;
        float w11 = wx * wy * aw;

        bool vx0 = (x0 >= 0) & (x0 < sh);
        bool vx1 = (x0 + 1 >= 0) & (x0 + 1 < sh);
        bool vy0 = (y0 >= 0) & (y0 < sh);
        bool vy1 = (y0 + 1 >= 0) & (y0 + 1 < sh);

        if (vx0 & vy0) acc += w00 * img_p[img_base + (long)(st + y0 * sh + x0) * HIDDEN];
        if (vx1 & vy0) acc += w10 * img_p[img_base + (long)(st + y0 * sh + x0 + 1) * HIDDEN];
        if (vx0 & vy1) acc += w01 * img_p[img_base + (long)(st + (y0 + 1) * sh + x0) * HIDDEN];
        if (vx1 & vy1) acc += w11 * img_p[img_base + (long)(st + (y0 + 1) * sh + x0 + 1) * HIDDEN];
    }

    // out[(b*NQ+n)*HIDDEN + h*32 + lane] == out[w*32 + lane]
    out[(long)w * CHD + lane] = acc;
}

// ---------------- launch ----------------
extern "C" void kernel_launch(void* const* d_in, const int* in_sizes, int n_in,
                              void* d_out, int out_size)
{
    const float* img    = (const float*)d_in[0];
    // d_in[1] = img_shapes (int32) — constant, hardcoded
    const float* queries = (const float*)d_in[2];
    const float* refpts  = (const float*)d_in[3];
    const float* W_img   = (const float*)d_in[4];
    const float* b_img   = (const float*)d_in[5];
    const float* W_q     = (const float*)d_in[6];
    const float* b_q     = (const float*)d_in[7];
    const float* W_out   = (const float*)d_in[8];
    const float* b_out   = (const float*)d_in[9];
    float* out = (float*)d_out;

    float *img_p, *qp, *attn, *hidden;
    float2* coords;
    cudaGetSymbolAddress((void**)&img_p,  g_img_p);
    cudaGetSymbolAddress((void**)&qp,     g_qp);
    cudaGetSymbolAddress((void**)&attn,   g_attn);
    cudaGetSymbolAddress((void**)&coords, g_coords);
    cudaGetSymbolAddress((void**)&hidden, g_hidden);

    // 1) img projection: [174080,256] @ [256,256] + b
    {
        dim3 grid(HIDDEN / 128, (BATCH * ITOT) / 128);
        sgemm_bias<<<grid, 256>>>(img, W_img, b_img, img_p,
                                  BATCH * ITOT, HIDDEN, EMBD);
    }
    // 2) query projection: [8192,256] @ [256,384] + b
    {
        dim3 grid(QPW / 128, (BATCH * NQ) / 128);
        sgemm_bias<<<grid, 256>>>(queries, W_q, b_q, qp,
                                  BATCH * NQ, QPW, EMBD);
    }
    // 3) softmax + sampling coords
    {
        int total = BATCH * NQ * HNUM;
        softmax_coords<<<(total + 255) / 256, 256>>>(qp, refpts, attn, coords);
    }
    // 4) bilinear sampling + attention reduce
    {
        int warps = BATCH * NQ * HNUM;          // 65536
        msda_sample<<<warps / 8, 256>>>(img_p, attn, coords, hidden);
    }
    // 5) output projection: [8192,256] @ [256,256] + b
    {
        dim3 grid(HIDDEN / 128, (BATCH * NQ) / 128);
        sgemm_bias<<<grid, 256>>>(hidden, W_out, b_out, out,
                                  BATCH * NQ, HIDDEN, EMBD);
    }
}

// round 3
// speedup vs baseline: 2.0471x; 2.0471x over previous
#include <cuda_runtime.h>
#include <cstdint>

// ---------------- problem constants (fixed by the reference) ----------------
#define EMBD   256
#define HIDDEN 256
#define HNUM   8
#define CHD    32
#define BATCH  8
#define NQ     1024
#define ITOT   21760           // 128^2 + 64^2 + 32^2 + 16^2
#define QPW    384             // H*L*P*3
#define GK     256             // K for every GEMM

// ---------------- scratch (no allocations allowed) ----------------
__device__ float  g_img_p[BATCH * ITOT * HIDDEN];     // projected pyramid  (~178 MB)
__device__ float  g_Wt1[HIDDEN * GK];                 // W_img^T  [N,K], tf32-rounded
__device__ float  g_Wt2[QPW * GK];                    // W_q^T    [N,K]
__device__ float  g_Wt3[EMBD * GK];                   // W_out^T  [N,K]
__device__ float  g_qp[BATCH * NQ * QPW];             // query projection
__device__ float  g_attn[BATCH * NQ * HNUM * 16];     // softmaxed attention
__device__ float2 g_coords[BATCH * NQ * HNUM * 16];   // sampling points (normalized)
__device__ float  g_hidden[BATCH * NQ * HIDDEN];      // sampled context

__constant__ int c_sh[4]    = {128, 64, 32, 16};
__constant__ int c_start[4] = {0, 16384, 20480, 21504};

// ---------------- helpers ----------------
__device__ __forceinline__ uint32_t smem_u32(const void* p) {
    uint32_t a;
    asm("{ .reg .u64 t; cvta.to.shared.u64 t, %1; cvt.u32.u64 %0, t; }" : "=r"(a) : "l"(p));
    return a;
}
__device__ __forceinline__ void cp16(uint32_t dst, const void* src) {
    asm volatile("cp.async.cg.shared.global [%0], [%1], 16;" :: "r"(dst), "l"(src));
}
__device__ __forceinline__ uint32_t f2tf32(float f) {
    uint32_t r;
    asm("cvt.rna.tf32.f32 %0, %1;" : "=r"(r) : "f"(f));
    return r;
}

// =============== mma.sync tf32 GEMM: C[M,N] = A[M,256] @ Wt[N,256]^T + bias ===============
// CTA tile 128x128, 8 warps in 2(M)x4(N), warp tile 64x32, k-step 16,
// double-buffered cp.async.  Wt is [N,K] row-major (pre-transposed, tf32-rounded).
// Requires M%128==0, N%128==0.

#define ROWPAD 20            // 16 floats + 4 pad (conflict-free fragment loads)

__global__ __launch_bounds__(256, 2) void mma_gemm(
    const float* __restrict__ A, const float* __restrict__ Wt,
    const float* __restrict__ bias, float* __restrict__ C,
    int M, int N)
{
    __shared__ float sm[2][256 * ROWPAD];   // [stage][(128 A rows + 128 B rows) * 20]

    const int tid = threadIdx.x;
    const int wid = tid >> 5;
    const int lane = tid & 31;
    const int g = lane >> 2;           // groupID 0..7
    const int tig = lane & 3;          // thread-in-group
    const int m0 = blockIdx.y * 128;
    const int n0 = blockIdx.x * 128;
    const int wm = (wid & 1) * 64;     // warp M offset
    const int wn = (wid >> 1) * 32;    // warp N offset

    float acc[4][4][4];
    #pragma unroll
    for (int i = 0; i < 4; i++)
        #pragma unroll
        for (int j = 0; j < 4; j++)
            #pragma unroll
            for (int r = 0; r < 4; r++) acc[i][j][r] = 0.f;

    const uint32_t smb0 = smem_u32(&sm[0][0]);
    const uint32_t smb1 = smem_u32(&sm[1][0]);

    // stage loader: 1024 16B-chunks (A: 512, B: 512), 4 per thread
    auto load_stage = [&](uint32_t smb, int kt) {
        #pragma unroll
        for (int i = 0; i < 4; i++) {
            int id = i * 256 + tid;
            int half = id >> 9;                 // 0 = A, 1 = B
            int rid = id & 511;
            int row = rid >> 2;
            int c = rid & 3;
            const float* src = half
                ? Wt + (size_t)(n0 + row) * GK + kt * 16 + c * 4
                : A  + (size_t)(m0 + row) * GK + kt * 16 + c * 4;
            cp16(smb + (uint32_t)((half * 128 + row) * ROWPAD + c * 4) * 4, src);
        }
    };

    load_stage(smb0, 0);
    asm volatile("cp.async.commit_group;" ::: "memory");

    #pragma unroll 1
    for (int kt = 0; kt < GK / 16; kt++) {
        const int buf = kt & 1;
        if (kt + 1 < GK / 16) {
            load_stage(buf ? smb0 : smb1, kt + 1);
            asm volatile("cp.async.commit_group;" ::: "memory");
            asm volatile("cp.async.wait_group 1;" ::: "memory");
        } else {
            asm volatile("cp.async.wait_group 0;" ::: "memory");
        }
        __syncthreads();

        const float* As = sm[buf];
        const float* Bs = sm[buf] + 128 * ROWPAD;

        #pragma unroll
        for (int ks = 0; ks < 2; ks++) {
            const int kb = ks * 8;
            uint32_t a[4][4], b[4][2];
            #pragma unroll
            for (int mf = 0; mf < 4; mf++) {
                int r = wm + mf * 16 + g;
                a[mf][0] = f2tf32(As[r * ROWPAD + kb + tig]);
                a[mf][1] = f2tf32(As[(r + 8) * ROWPAD + kb + tig]);
                a[mf][2] = f2tf32(As[r * ROWPAD + kb + tig + 4]);
                a[mf][3] = f2tf32(As[(r + 8) * ROWPAD + kb + tig + 4]);
            }
            #pragma unroll
            for (int nf = 0; nf < 4; nf++) {
                int r = wn + nf * 8 + g;
                b[nf][0] = __float_as_uint(Bs[r * ROWPAD + kb + tig]);     // pre-rounded
                b[nf][1] = __float_as_uint(Bs[r * ROWPAD + kb + tig + 4]);
            }
            #pragma unroll
            for (int mf = 0; mf < 4; mf++)
                #pragma unroll
                for (int nf = 0; nf < 4; nf++) {
                    asm volatile(
                        "mma.sync.aligned.m16n8k8.row.col.f32.tf32.tf32.f32 "
                        "{%0,%1,%2,%3}, {%4,%5,%6,%7}, {%8,%9}, {%0,%1,%2,%3};"
                        : "+f"(acc[mf][nf][0]), "+f"(acc[mf][nf][1]),
                          "+f"(acc[mf][nf][2]), "+f"(acc[mf][nf][3])
                        : "r"(a[mf][0]), "r"(a[mf][1]), "r"(a[mf][2]), "r"(a[mf][3]),
                          "r"(b[nf][0]), "r"(b[nf][1]));
                }
        }
        __syncthreads();
    }

    // epilogue: add bias, write float2 pairs
    #pragma unroll
    for (int nf = 0; nf < 4; nf++) {
        const int col = n0 + wn + nf * 8 + tig * 2;
        const float2 bb = *(const float2*)(bias + col);
        #pragma unroll
        for (int mf = 0; mf < 4; mf++) {
            const int row = m0 + wm + mf * 16 + g;
            float2 v0 = make_float2(acc[mf][nf][0] + bb.x, acc[mf][nf][1] + bb.y);
            float2 v1 = make_float2(acc[mf][nf][2] + bb.x, acc[mf][nf][3] + bb.y);
            *(float2*)(C + (size_t)row * N + col) = v0;
            *(float2*)(C + (size_t)(row + 8) * N + col) = v1;
        }
    }
}

// W [K=256, N] row-major  ->  Wt [N, K] row-major, tf32-rounded
__global__ void pack_wt(const float* __restrict__ W, float* __restrict__ Wt, int N) {
    __shared__ float t[32][33];
    int bx = blockIdx.x * 32;   // n tile
    int by = blockIdx.y * 32;   // k tile
    int x = threadIdx.x, y = threadIdx.y;
    #pragma unroll
    for (int i = 0; i < 32; i += 8)
        t[y + i][x] = W[(size_t)(by + y + i) * N + bx + x];   // t[k_local][n_local]
    __syncthreads();
    #pragma unroll
    for (int i = 0; i < 32; i += 8) {
        float v = t[x][y + i];   // W[k=by+x][n=bx+y+i]
        Wt[(size_t)(bx + y + i) * GK + by + x] = __uint_as_float(f2tf32(v));
    }
}

// ---------------- softmax + sampling-coordinate precompute ----------------
__global__ void softmax_coords(const float* __restrict__ qp,
                               const float* __restrict__ refpts,
                               float* __restrict__ attn,
                               float2* __restrict__ coords)
{
    int t = blockIdx.x * blockDim.x + threadIdx.x;
    if (t >= BATCH * NQ * HNUM) return;
    int bn = t / HNUM;

    const float* q = qp + (size_t)t * 48;

    float lg[16];
    float mx = -1e30f;
    #pragma unroll
    for (int s = 0; s < 16; s++) { lg[s] = q[s * 3 + 2]; mx = fmaxf(mx, lg[s]); }
    float sum = 0.f;
    #pragma unroll
    for (int s = 0; s < 16; s++) { lg[s] = expf(lg[s] - mx); sum += lg[s]; }
    float inv = 1.0f / sum;

    float rx = refpts[bn * 2 + 0];
    float ry = refpts[bn * 2 + 1];

    #pragma unroll
    for (int s = 0; s < 16; s++) {
        int l = s >> 2;
        float sh = (float)c_sh[l];
        attn[(size_t)t * 16 + s] = lg[s] * inv;
        float ox = q[s * 3 + 0];
        float oy = q[s * 3 + 1];
        coords[(size_t)t * 16 + s] = make_float2(rx + ox / sh, ry + oy / sh);
    }
}

// ---------------- bilinear sampling + attention reduce ----------------
__global__ __launch_bounds__(256) void msda_sample(
    const float* __restrict__ img_p,
    const float* __restrict__ attn,
    const float2* __restrict__ coords,
    float* __restrict__ out)
{
    int w = blockIdx.x * 8 + (threadIdx.x >> 5);
    int lane = threadIdx.x & 31;

    int h = w % HNUM;
    int b = w / (NQ * HNUM);

    const size_t img_base = (size_t)b * ITOT * HIDDEN + h * CHD + lane;
    const float*  ap = attn   + (size_t)w * 16;
    const float2* cp = coords + (size_t)w * 16;

    float acc = 0.f;

    #pragma unroll
    for (int s = 0; s < 16; s++) {
        int l = s >> 2;
        int sh = c_sh[l];
        float fs = (float)sh;
        int st = c_start[l];

        float aw = ap[s];
        float2 c = cp[s];

        float x = c.x * fs - 0.5f;
        float y = c.y * fs - 0.5f;
        float x0f = floorf(x), y0f = floorf(y);
        int x0 = (int)x0f, y0 = (int)y0f;
        float wx = x - x0f, wy = y - y0f;

        float w00 = (1.f - wx) * (1.f - wy) * aw;
        float w10 = wx * (1.f - wy) * aw;
        float w01 = (1.f - wx) * wy * aw;
        float w11 = wx * wy * aw;

        bool vx0 = (x0 >= 0) & (x0 < sh);
        bool vx1 = (x0 + 1 >= 0) & (x0 + 1 < sh);
        bool vy0 = (y0 >= 0) & (y0 < sh);
        bool vy1 = (y0 + 1 >= 0) & (y0 + 1 < sh);

        if (vx0 & vy0) acc += w00 * img_p[img_base + (size_t)(st + y0 * sh + x0) * HIDDEN];
        if (vx1 & vy0) acc += w10 * img_p[img_base + (size_t)(st + y0 * sh + x0 + 1) * HIDDEN];
        if (vx0 & vy1) acc += w01 * img_p[img_base + (size_t)(st + (y0 + 1) * sh + x0) * HIDDEN];
        if (vx1 & vy1) acc += w11 * img_p[img_base + (size_t)(st + (y0 + 1) * sh + x0 + 1) * HIDDEN];
    }

    out[(size_t)w * CHD + lane] = acc;
}

// ---------------- launch ----------------
extern "C" void kernel_launch(void* const* d_in, const int* in_sizes, int n_in,
                              void* d_out, int out_size)
{
    const float* img     = (const float*)d_in[0];
    const float* queries = (const float*)d_in[2];
    const float* refpts  = (const float*)d_in[3];
    const float* W_img   = (const float*)d_in[4];
    const float* b_img   = (const float*)d_in[5];
    const float* W_q     = (const float*)d_in[6];
    const float* b_q     = (const float*)d_in[7];
    const float* W_out   = (const float*)d_in[8];
    const float* b_out   = (const float*)d_in[9];
    float* out = (float*)d_out;

    float *img_p, *qp, *attn, *hidden, *Wt1, *Wt2, *Wt3;
    float2* coords;
    cudaGetSymbolAddress((void**)&img_p,  g_img_p);
    cudaGetSymbolAddress((void**)&qp,     g_qp);
    cudaGetSymbolAddress((void**)&attn,   g_attn);
    cudaGetSymbolAddress((void**)&coords, g_coords);
    cudaGetSymbolAddress((void**)&hidden, g_hidden);
    cudaGetSymbolAddress((void**)&Wt1,    g_Wt1);
    cudaGetSymbolAddress((void**)&Wt2,    g_Wt2);
    cudaGetSymbolAddress((void**)&Wt3,    g_Wt3);

    // 0) pack weights: transpose to [N,K] + tf32 rounding
    {
        dim3 blk(32, 8);
        pack_wt<<<dim3(HIDDEN / 32, GK / 32), blk>>>(W_img, Wt1, HIDDEN);
        pack_wt<<<dim3(QPW    / 32, GK / 32), blk>>>(W_q,   Wt2, QPW);
        pack_wt<<<dim3(EMBD   / 32, GK / 32), blk>>>(W_out, Wt3, EMBD);
    }
    // 1) img projection: [174080,256] @ [256,256] + b
    mma_gemm<<<dim3(HIDDEN / 128, (BATCH * ITOT) / 128), 256>>>(
        img, Wt1, b_img, img_p, BATCH * ITOT, HIDDEN);
    // 2) query projection: [8192,256] @ [256,384] + b
    mma_gemm<<<dim3(QPW / 128, (BATCH * NQ) / 128), 256>>>(
        queries, Wt2, b_q, qp, BATCH * NQ, QPW);
    // 3) softmax + sampling coords
    {
        int total = BATCH * NQ * HNUM;
        softmax_coords<<<(total + 255) / 256, 256>>>(qp, refpts, attn, coords);
    }
    // 4) bilinear sampling + attention reduce
    msda_sample<<<(BATCH * NQ * HNUM) / 8, 256>>>(img_p, attn, coords, hidden);
    // 5) output projection: [8192,256] @ [256,256] + b
    mma_gemm<<<dim3(HIDDEN / 128, (BATCH * NQ) / 128), 256>>>(
        hidden, Wt3, b_out, out, BATCH * NQ, HIDDEN);
}